// round 4
// baseline (speedup 1.0000x reference)
#include <cuda_runtime.h>
#include <math.h>

#define BB 8
#define NN 2048
#define BN (BB*NN)
#define KK 30
#define CAP 288          // candidate buffer capacity

// ---- output layout (float32, tuple arrays concatenated, flattened C-order) ----
#define NS_OFF 0                         // node_scalar (8,2048,7)      = 114688
#define NV_OFF 114688                    // node_vector (8,2048,3,3)    = 147456
#define DN_OFF 262144                    // D_neighbors (8,2048,30)     = 491520
#define EI_OFF 753664                    // E_idx       (8,2048,30)     = 491520
#define CM_OFF 1245184                   // cm_nb       (8,2048,30)     = 491520
#define RM_OFF 1736704                   // rm_nb       (8,2048,30)     = 491520

// ---- scratch (__device__ globals: no allocation allowed) ----
__device__ float4        g_xca[BN];      // x,y,z of CA atom; w = coord_mask (0/1)
__device__ unsigned char g_rm[BN];       // rm = !padding_mask
__device__ int           g_fmt;          // 0=uint8, 1=int32, 2=float32 bool storage

// ---------------------------------------------------------------------------
// Detect how the harness serialized the bool masks (coord_mask is ~90% true).
// ---------------------------------------------------------------------------
__global__ void detect_kernel(const unsigned char* cm) {
    __shared__ int s3F, sOff;
    if (threadIdx.x == 0) { s3F = 0; sOff = 0; }
    __syncthreads();
    for (int i = threadIdx.x; i < 4096; i += blockDim.x) {
        unsigned char v = cm[i];
        int r = i & 3;
        if (r != 0 && v != 0) {
            atomicOr(&sOff, 1);
            if (r == 3 && v == 0x3F) atomicOr(&s3F, 1);
        }
    }
    __syncthreads();
    if (threadIdx.x == 0) g_fmt = s3F ? 2 : (sOff ? 0 : 1);
}

__device__ __forceinline__ bool read_mask(const void* p, int i, int fmt) {
    if (fmt == 2) return ((const float*)p)[i] != 0.0f;
    if (fmt == 1) return ((const int*)p)[i]   != 0;
    return ((const unsigned char*)p)[i] != 0;
}

// ---------------------------------------------------------------------------
// Pack CA coords + coord_mask into float4, and rm into bytes.
// ---------------------------------------------------------------------------
__global__ void pack_kernel(const float* __restrict__ coords,
                            const void* __restrict__ cm,
                            const void* __restrict__ pm) {
    int idx = blockIdx.x * blockDim.x + threadIdx.x;
    if (idx >= BN) return;
    int fmt = g_fmt;
    float4 v;
    v.x = coords[idx * 9 + 3];
    v.y = coords[idx * 9 + 4];
    v.z = coords[idx * 9 + 5];
    v.w = read_mask(cm, idx, fmt) ? 1.0f : 0.0f;
    g_xca[idx] = v;
    g_rm[idx]  = read_mask(pm, idx, fmt) ? 0 : 1;   // rm = ~padding
}

// ---- small vec helpers (match jax: v / sqrt(dot(v,v) + 1e-8)) ----
__device__ __forceinline__ void nrm3(float& x, float& y, float& z) {
    float inv = 1.0f / sqrtf(x*x + y*y + z*z + 1e-8f);
    x *= inv; y *= inv; z *= inv;
}
__device__ __forceinline__ void cross3(float ax, float ay, float az,
                                       float bx, float by, float bz,
                                       float& cx, float& cy, float& cz) {
    cx = ay*bz - az*by;
    cy = az*bx - ax*bz;
    cz = ax*by - ay*bx;
}

// ---------------------------------------------------------------------------
// node_scalar (dihedrals + mask) and node_vector (fwd, bwd, sidechain)
// ---------------------------------------------------------------------------
__global__ void features_kernel(const float* __restrict__ coords,
                                float* __restrict__ out) {
    int idx = blockIdx.x * blockDim.x + threadIdx.x;
    if (idx >= BN) return;
    int b = idx >> 11, n = idx & (NN - 1);
    const float* Xf = coords + (size_t)b * NN * 9;   // (3N, 3) flat view

    float cosv[3], sinv[3];
    #pragma unroll
    for (int t = 0; t < 3; t++) {
        int f = 3 * n + t;
        if (f < 1 || f >= 3 * NN - 2) { cosv[t] = 1.0f; sinv[t] = 0.0f; continue; }
        const float* p0 = Xf + (size_t)(f - 1) * 3;
        const float* p1 = Xf + (size_t)(f    ) * 3;
        const float* p2 = Xf + (size_t)(f + 1) * 3;
        const float* p3 = Xf + (size_t)(f + 2) * 3;
        float u2x = p1[0]-p0[0], u2y = p1[1]-p0[1], u2z = p1[2]-p0[2];
        float u1x = p2[0]-p1[0], u1y = p2[1]-p1[1], u1z = p2[2]-p1[2];
        float u0x = p3[0]-p2[0], u0y = p3[1]-p2[1], u0z = p3[2]-p2[2];
        nrm3(u2x,u2y,u2z); nrm3(u1x,u1y,u1z); nrm3(u0x,u0y,u0z);
        float n2x,n2y,n2z, n1x,n1y,n1z;
        cross3(u2x,u2y,u2z, u1x,u1y,u1z, n2x,n2y,n2z); nrm3(n2x,n2y,n2z);
        cross3(u1x,u1y,u1z, u0x,u0y,u0z, n1x,n1y,n1z); nrm3(n1x,n1y,n1z);
        float cD = n2x*n1x + n2y*n1y + n2z*n1z;
        cD = fminf(fmaxf(cD, -1.0f + 1e-7f), 1.0f - 1e-7f);
        float sg = u2x*n1x + u2y*n1y + u2z*n1z;
        float s  = (sg > 0.0f) ? 1.0f : ((sg < 0.0f) ? -1.0f : 0.0f);
        float D  = s * acosf(cD);
        cosv[t] = cosf(D);
        sinv[t] = sinf(D);
    }

    float4 xc = g_xca[idx];
    float* ns = out + NS_OFF + (size_t)idx * 7;
    ns[0] = cosv[0]; ns[1] = cosv[1]; ns[2] = cosv[2];
    ns[3] = sinv[0]; ns[4] = sinv[1]; ns[5] = sinv[2];
    ns[6] = xc.w;

    float fx = 0.f, fy = 0.f, fz = 0.f, bx = 0.f, by = 0.f, bz = 0.f;
    if (n < NN - 1) {
        float4 xn = g_xca[idx + 1];
        fx = xn.x - xc.x; fy = xn.y - xc.y; fz = xn.z - xc.z;
        nrm3(fx, fy, fz);
    }
    if (n > 0) {
        float4 xp = g_xca[idx - 1];
        bx = xp.x - xc.x; by = xp.y - xc.y; bz = xp.z - xc.z;
        nrm3(bx, by, bz);
    }

    const float* at = coords + (size_t)idx * 9;
    float ox = at[3], oy = at[4], oz = at[5];
    float nx = at[0]-ox, ny = at[1]-oy, nz = at[2]-oz;
    float cx = at[6]-ox, cy = at[7]-oy, cz = at[8]-oz;
    nrm3(cx,cy,cz); nrm3(nx,ny,nz);
    float bix = cx+nx, biy = cy+ny, biz = cz+nz; nrm3(bix,biy,biz);
    float px,py,pz; cross3(cx,cy,cz, nx,ny,nz, px,py,pz); nrm3(px,py,pz);
    const float S13 = 0.5773502691896258f;   // sqrt(1/3)
    const float S23 = 0.8164965809277260f;   // sqrt(2/3)
    float sx = -bix*S13 - px*S23;
    float sy = -biy*S13 - py*S23;
    float sz = -biz*S13 - pz*S23;

    float* nv = out + NV_OFF + (size_t)idx * 9;
    nv[0]=fx; nv[1]=fy; nv[2]=fz;
    nv[3]=bx; nv[4]=by; nv[5]=bz;
    nv[6]=sx; nv[7]=sy; nv[8]=sz;
}

// ---------------------------------------------------------------------------
// Top-k via exact radix-select on composite keys (D_adjust bits << 32 | j).
// dadj lives in 8 registers per thread (j is implicit: tid + q*256).
// Histogram is bank-rotated: bin -> ((bin&7)<<8)|(bin>>3) so the superbin
// scan (thread tid sums bins tid*8..tid*8+7) is conflict-free.
// A generic 11-bit/level radix refinement loop guarantees <= CAP candidates
// for ANY input (keys unique -> terminates); it runs exactly once for this
// data. Candidate set is downward-closed in key order, so O(C^2) ranking
// reproduces jax.lax.top_k (ascending value, ties by lowest index) exactly.
// ---------------------------------------------------------------------------
__device__ __forceinline__ void emit(int row, int base, float4 xi, bool cmi,
                                     int rank, unsigned long long k,
                                     float* __restrict__ out) {
    int j = (int)(unsigned)(k & 0xffffffffu);
    float4 xj = g_xca[base + j];
    float dx = xj.x - xi.x, dy = xj.y - xi.y, dz = xj.z - xi.z;
    float d  = sqrtf(dx*dx + dy*dy + dz*dz + 1e-8f);
    float D  = (cmi && xj.w != 0.0f) ? d : 0.0f;
    size_t o = (size_t)row * KK + rank;
    out[DN_OFF + o] = D;
    out[EI_OFF + o] = (float)j;
    out[CM_OFF + o] = (D < 50000000.0f)   ? 1.0f : 0.0f;
    out[RM_OFF + o] = (D < 5000000000.0f) ? 1.0f : 0.0f;
}

__global__ void __launch_bounds__(256) topk_kernel(const int* __restrict__ res_idx,
                                                   float* __restrict__ out) {
    __shared__ unsigned int       hist[2048];    // 8 KB, bank-rotated layout
    __shared__ unsigned long long cand[CAP];     // 2.25 KB
    __shared__ unsigned int       wtot[8];
    __shared__ int s_cnt, s_piv, s_sb, s_excl, s_histpiv;

    int row = blockIdx.x;           // b*2048 + i
    int b   = row >> 11;
    int i   = row & (NN - 1);
    int tid = threadIdx.x;
    int lane = tid & 31, wid = tid >> 5;
    int base = b << 11;

    float4 xi = g_xca[row];
    int   ri  = res_idx[row];
    bool  rmi = g_rm[row] != 0;
    bool  cmi = xi.w != 0.0f;

    // ---- phase 1: compute D_adjust for 8 j's, keep in registers ----
    float dj[8];
    #pragma unroll
    for (int q = 0; q < 8; q++) {
        int j = tid + q * 256;
        float4 xj = g_xca[base + j];
        float dx = xj.x - xi.x, dy = xj.y - xi.y, dz = xj.z - xi.z;
        float d  = sqrtf(dx*dx + dy*dy + dz*dz + 1e-8f);
        bool cm2 = cmi && (xj.w != 0.0f);
        float D  = cm2 ? d : 0.0f;
        int  rj  = res_idx[base + j];
        int  dr  = ri - rj; if (dr < 0) dr = -dr;
        float dadj = (dr <= 3) ? 0.0f : D;          // D_cov = D * (1 - cov)
        if (!cm2) {
            int ds = i - j; if (ds < 0) ds = -ds;
            dadj += 100000000.0f + (float)ds * 1000000.0f;
        }
        if (!(rmi && (g_rm[base + j] != 0))) dadj += 10000000000.0f;
        dj[q] = dadj;
    }

    // ---- radix refinement loop (body runs once for real data) ----
    unsigned long long fmask = 0, prefix = 0;
    int shift = 53;
    int kbelow = 0;

    for (;;) {
        // zero histogram (2 x STS.128 per thread) + counter
        ((uint4*)hist)[tid]       = make_uint4(0u, 0u, 0u, 0u);
        ((uint4*)hist)[tid + 256] = make_uint4(0u, 0u, 0u, 0u);
        if (tid == 0) s_cnt = 0;
        __syncthreads();

        // histogram the current 11-bit digit of matching keys
        #pragma unroll
        for (int q = 0; q < 8; q++) {
            unsigned long long k =
                ((unsigned long long)__float_as_uint(dj[q]) << 32)
                | (unsigned)(tid + q * 256);
            if ((k & fmask) == prefix) {
                unsigned d = (unsigned)((k >> shift) & 2047u);
                atomicAdd(&hist[((d & 7u) << 8) | (d >> 3)], 1u);
            }
        }
        __syncthreads();

        // superbin sums: thread tid covers original bins [tid*8, tid*8+8)
        // rotated layout -> reads hist[(q<<8)|tid], conflict-free
        unsigned v = 0;
        #pragma unroll
        for (int q = 0; q < 8; q++) v += hist[(q << 8) | tid];
        unsigned sc = v;
        #pragma unroll
        for (int o = 1; o < 32; o <<= 1) {
            unsigned n = __shfl_up_sync(0xffffffffu, sc, o);
            if (lane >= o) sc += n;
        }
        if (lane == 31) wtot[wid] = sc;
        __syncthreads();
        if (wid == 0) {
            unsigned w = (lane < 8) ? wtot[lane] : 0;
            #pragma unroll
            for (int o = 1; o < 8; o <<= 1) {
                unsigned n = __shfl_up_sync(0xffffffffu, w, o);
                if (lane >= o) w += n;
            }
            if (lane < 8) wtot[lane] = w;
        }
        __syncthreads();

        int kneed = KK - kbelow;
        unsigned incl = sc + (wid ? wtot[wid - 1] : 0);
        unsigned excl = incl - v;
        if ((int)incl >= kneed && (int)excl < kneed) { s_sb = tid; s_excl = (int)excl; }
        __syncthreads();
        if (tid == 0) {
            int sb = s_sb;
            unsigned cum = (unsigned)s_excl;
            int pd = sb * 8 + 7; unsigned hp = hist[(7u << 8) | sb];
            #pragma unroll
            for (int q = 0; q < 8; q++) {
                unsigned h = hist[(q << 8) | sb];
                if (cum + h >= (unsigned)kneed) { pd = sb * 8 + q; hp = h; break; }
                cum += h;
            }
            s_piv = pd; s_excl = (int)cum; s_histpiv = (int)hp;
        }
        __syncthreads();

        int below_total = kbelow + s_excl;              // keys strictly below pivot prefix
        unsigned long long nfmask  = fmask | (2047ULL << shift);
        unsigned long long nprefix = prefix | ((unsigned long long)s_piv << shift);

        if (below_total + s_histpiv <= CAP || shift == 0) {
            // compact: trunc(key) <= pivot prefix  (downward-closed candidate set)
            #pragma unroll
            for (int q = 0; q < 8; q++) {
                unsigned long long k =
                    ((unsigned long long)__float_as_uint(dj[q]) << 32)
                    | (unsigned)(tid + q * 256);
                if ((k & nfmask) <= nprefix) {
                    int pos = atomicAdd(&s_cnt, 1);
                    if (pos < CAP) cand[pos] = k;
                }
            }
            __syncthreads();
            break;
        }
        fmask = nfmask; prefix = nprefix;
        shift = (shift >= 11) ? shift - 11 : 0;
        kbelow = below_total;
        __syncthreads();
    }

    // ---- exact rank by O(C^2) broadcast comparisons ----
    int C = s_cnt; if (C > CAP) C = CAP;
    for (int t = tid; t < C; t += 256) {
        unsigned long long k = cand[t];
        int rank = 0;
        for (int c = 0; c < C; c++) rank += (cand[c] < k);
        if (rank < KK) emit(row, base, xi, cmi, rank, k, out);
    }
}

extern "C" void kernel_launch(void* const* d_in, const int* in_sizes, int n_in,
                              void* d_out, int out_size) {
    const float* coords = (const float*)d_in[0];
    const void*  cm     = d_in[1];
    const int*   ridx   = (const int*)d_in[2];
    const void*  pm     = d_in[3];
    float* out = (float*)d_out;

    detect_kernel<<<1, 128>>>((const unsigned char*)cm);
    pack_kernel<<<(BN + 255) / 256, 256>>>(coords, cm, pm);
    features_kernel<<<(BN + 255) / 256, 256>>>(coords, out);
    topk_kernel<<<BN, 256>>>(ridx, out);
}

// round 5
// speedup vs baseline: 1.6837x; 1.6837x over previous
#include <cuda_runtime.h>
#include <math.h>

#define BB 8
#define NN 2048
#define BN (BB*NN)
#define KK 30
#define CAP 288          // candidate buffer capacity

// ---- output layout (float32, tuple arrays concatenated, flattened C-order) ----
#define NS_OFF 0                         // node_scalar (8,2048,7)      = 114688
#define NV_OFF 114688                    // node_vector (8,2048,3,3)    = 147456
#define DN_OFF 262144                    // D_neighbors (8,2048,30)     = 491520
#define EI_OFF 753664                    // E_idx       (8,2048,30)     = 491520
#define CM_OFF 1245184                   // cm_nb       (8,2048,30)     = 491520
#define RM_OFF 1736704                   // rm_nb       (8,2048,30)     = 491520

// ---- scratch (__device__ globals: no allocation allowed) ----
// w lane packs: (res_idx << 2) | (rm << 1) | cm   (as int bits)
__device__ float4 g_xca[BN];
__device__ int    g_fmt;                 // 0=uint8, 1=int32, 2=float32 bool storage

// ---------------------------------------------------------------------------
// Detect how the harness serialized the bool masks (coord_mask is ~90% true).
// ---------------------------------------------------------------------------
__global__ void detect_kernel(const unsigned char* cm) {
    __shared__ int s3F, sOff;
    if (threadIdx.x == 0) { s3F = 0; sOff = 0; }
    __syncthreads();
    for (int i = threadIdx.x; i < 4096; i += blockDim.x) {
        unsigned char v = cm[i];
        int r = i & 3;
        if (r != 0 && v != 0) {
            atomicOr(&sOff, 1);
            if (r == 3 && v == 0x3F) atomicOr(&s3F, 1);
        }
    }
    __syncthreads();
    if (threadIdx.x == 0) g_fmt = s3F ? 2 : (sOff ? 0 : 1);
}

__device__ __forceinline__ bool read_mask(const void* p, int i, int fmt) {
    if (fmt == 2) return ((const float*)p)[i] != 0.0f;
    if (fmt == 1) return ((const int*)p)[i]   != 0;
    return ((const unsigned char*)p)[i] != 0;
}

// ---------------------------------------------------------------------------
// Pack CA coords + (res_idx, rm, cm) into one float4 per residue.
// ---------------------------------------------------------------------------
__global__ void pack_kernel(const float* __restrict__ coords,
                            const void* __restrict__ cm,
                            const int*  __restrict__ res_idx,
                            const void* __restrict__ pm) {
    int idx = blockIdx.x * blockDim.x + threadIdx.x;
    if (idx >= BN) return;
    int fmt = g_fmt;
    int w = (res_idx[idx] << 2)
          | (read_mask(pm, idx, fmt) ? 0 : 2)       // rm = ~padding
          | (read_mask(cm, idx, fmt) ? 1 : 0);
    float4 v;
    v.x = coords[idx * 9 + 3];
    v.y = coords[idx * 9 + 4];
    v.z = coords[idx * 9 + 5];
    v.w = __int_as_float(w);
    g_xca[idx] = v;
}

// ---- small vec helpers (match jax: v / sqrt(dot(v,v) + 1e-8)) ----
__device__ __forceinline__ void nrm3(float& x, float& y, float& z) {
    float inv = 1.0f / sqrtf(x*x + y*y + z*z + 1e-8f);
    x *= inv; y *= inv; z *= inv;
}
__device__ __forceinline__ void cross3(float ax, float ay, float az,
                                       float bx, float by, float bz,
                                       float& cx, float& cy, float& cz) {
    cx = ay*bz - az*by;
    cy = az*bx - ax*bz;
    cz = ax*by - ay*bx;
}

// ---------------------------------------------------------------------------
// node_scalar (dihedrals + mask) and node_vector (fwd, bwd, sidechain)
// ---------------------------------------------------------------------------
__global__ void features_kernel(const float* __restrict__ coords,
                                float* __restrict__ out) {
    int idx = blockIdx.x * blockDim.x + threadIdx.x;
    if (idx >= BN) return;
    int b = idx >> 11, n = idx & (NN - 1);
    const float* Xf = coords + (size_t)b * NN * 9;   // (3N, 3) flat view

    float cosv[3], sinv[3];
    #pragma unroll
    for (int t = 0; t < 3; t++) {
        int f = 3 * n + t;
        if (f < 1 || f >= 3 * NN - 2) { cosv[t] = 1.0f; sinv[t] = 0.0f; continue; }
        const float* p0 = Xf + (size_t)(f - 1) * 3;
        const float* p1 = Xf + (size_t)(f    ) * 3;
        const float* p2 = Xf + (size_t)(f + 1) * 3;
        const float* p3 = Xf + (size_t)(f + 2) * 3;
        float u2x = p1[0]-p0[0], u2y = p1[1]-p0[1], u2z = p1[2]-p0[2];
        float u1x = p2[0]-p1[0], u1y = p2[1]-p1[1], u1z = p2[2]-p1[2];
        float u0x = p3[0]-p2[0], u0y = p3[1]-p2[1], u0z = p3[2]-p2[2];
        nrm3(u2x,u2y,u2z); nrm3(u1x,u1y,u1z); nrm3(u0x,u0y,u0z);
        float n2x,n2y,n2z, n1x,n1y,n1z;
        cross3(u2x,u2y,u2z, u1x,u1y,u1z, n2x,n2y,n2z); nrm3(n2x,n2y,n2z);
        cross3(u1x,u1y,u1z, u0x,u0y,u0z, n1x,n1y,n1z); nrm3(n1x,n1y,n1z);
        float cD = n2x*n1x + n2y*n1y + n2z*n1z;
        cD = fminf(fmaxf(cD, -1.0f + 1e-7f), 1.0f - 1e-7f);
        float sg = u2x*n1x + u2y*n1y + u2z*n1z;
        float s  = (sg > 0.0f) ? 1.0f : ((sg < 0.0f) ? -1.0f : 0.0f);
        float D  = s * acosf(cD);
        cosv[t] = cosf(D);
        sinv[t] = sinf(D);
    }

    float4 xc = g_xca[idx];
    float* ns = out + NS_OFF + (size_t)idx * 7;
    ns[0] = cosv[0]; ns[1] = cosv[1]; ns[2] = cosv[2];
    ns[3] = sinv[0]; ns[4] = sinv[1]; ns[5] = sinv[2];
    ns[6] = (__float_as_int(xc.w) & 1) ? 1.0f : 0.0f;

    float fx = 0.f, fy = 0.f, fz = 0.f, bx = 0.f, by = 0.f, bz = 0.f;
    if (n < NN - 1) {
        float4 xn = g_xca[idx + 1];
        fx = xn.x - xc.x; fy = xn.y - xc.y; fz = xn.z - xc.z;
        nrm3(fx, fy, fz);
    }
    if (n > 0) {
        float4 xp = g_xca[idx - 1];
        bx = xp.x - xc.x; by = xp.y - xc.y; bz = xp.z - xc.z;
        nrm3(bx, by, bz);
    }

    const float* at = coords + (size_t)idx * 9;
    float ox = at[3], oy = at[4], oz = at[5];
    float nx = at[0]-ox, ny = at[1]-oy, nz = at[2]-oz;
    float cx = at[6]-ox, cy = at[7]-oy, cz = at[8]-oz;
    nrm3(cx,cy,cz); nrm3(nx,ny,nz);
    float bix = cx+nx, biy = cy+ny, biz = cz+nz; nrm3(bix,biy,biz);
    float px,py,pz; cross3(cx,cy,cz, nx,ny,nz, px,py,pz); nrm3(px,py,pz);
    const float S13 = 0.5773502691896258f;   // sqrt(1/3)
    const float S23 = 0.8164965809277260f;   // sqrt(2/3)
    float sx = -bix*S13 - px*S23;
    float sy = -biy*S13 - py*S23;
    float sz = -biz*S13 - pz*S23;

    float* nv = out + NV_OFF + (size_t)idx * 9;
    nv[0]=fx; nv[1]=fy; nv[2]=fz;
    nv[3]=bx; nv[4]=by; nv[5]=bz;
    nv[6]=sx; nv[7]=sy; nv[8]=sz;
}

// ---------------------------------------------------------------------------
// Top-k via exact radix-select on the FLOAT BITS of D_adjust (dadj >= 0 ->
// uint bits are order-monotone). Values live in 8 uint registers per thread
// (j implicit: tid + q*256). 64-bit keys ((bits<<32)|j) are built only for
// the compacted candidates; O(C^2) ranking there reproduces jax.lax.top_k
// order (ascending value, ties by lowest index) exactly.
// Histogram is bank-rotated: bin -> ((bin&7)<<8)|(bin>>3), so the superbin
// scan is conflict-free. Refinement levels over bit ranges [31:21],[20:10],
// [9:0] guarantee <= CAP candidates for any input except >CAP identical
// floats at the rank boundary, which falls back to exact min-extraction.
// ---------------------------------------------------------------------------
__device__ __forceinline__ unsigned long long umin64(unsigned long long a,
                                                     unsigned long long b) {
    return a < b ? a : b;
}

__device__ __forceinline__ void emit(int row, int base, float4 xi, bool cmi,
                                     int rank, unsigned long long k,
                                     float* __restrict__ out) {
    int j = (int)(unsigned)(k & 0xffffffffu);
    float4 xj = g_xca[base + j];
    float dx = xj.x - xi.x, dy = xj.y - xi.y, dz = xj.z - xi.z;
    float d  = sqrtf(dx*dx + dy*dy + dz*dz + 1e-8f);
    float D  = (cmi && (__float_as_int(xj.w) & 1)) ? d : 0.0f;
    size_t o = (size_t)row * KK + rank;
    out[DN_OFF + o] = D;
    out[EI_OFF + o] = (float)j;
    out[CM_OFF + o] = (D < 50000000.0f)   ? 1.0f : 0.0f;
    out[RM_OFF + o] = (D < 5000000000.0f) ? 1.0f : 0.0f;
}

__global__ void __launch_bounds__(256) topk_kernel(float* __restrict__ out) {
    __shared__ unsigned int       hist[2048];    // 8 KB, bank-rotated layout
    __shared__ unsigned long long cand[CAP];     // 2.25 KB
    __shared__ unsigned int       wtot[8];
    __shared__ unsigned long long s_win;
    __shared__ int s_cnt, s_piv, s_sb, s_excl, s_histpiv;

    int row = blockIdx.x;           // b*2048 + i
    int b   = row >> 11;
    int i   = row & (NN - 1);
    int tid = threadIdx.x;
    int lane = tid & 31, wid = tid >> 5;
    int base = b << 11;

    float4 xi = g_xca[row];
    int  wi  = __float_as_int(xi.w);
    int  ri  = wi >> 2;
    bool rmi = (wi & 2) != 0;
    bool cmi = (wi & 1) != 0;

    // ---- phase 1: compute D_adjust bits for 8 j's, keep in registers ----
    unsigned bj[8];
    #pragma unroll
    for (int q = 0; q < 8; q++) {
        int j = tid + q * 256;
        float4 xj = g_xca[base + j];
        float dx = xj.x - xi.x, dy = xj.y - xi.y, dz = xj.z - xi.z;
        float d  = sqrtf(dx*dx + dy*dy + dz*dz + 1e-8f);
        int  wj  = __float_as_int(xj.w);
        bool cm2 = cmi && (wj & 1);
        float D  = cm2 ? d : 0.0f;
        int  dr  = ri - (wj >> 2); if (dr < 0) dr = -dr;
        float dadj = (dr <= 3) ? 0.0f : D;          // D_cov = D * (1 - cov)
        if (!cm2) {
            int ds = i - j; if (ds < 0) ds = -ds;
            dadj += 100000000.0f + (float)ds * 1000000.0f;
        }
        if (!(rmi && (wj & 2))) dadj += 10000000000.0f;
        bj[q] = __float_as_uint(dadj);
    }

    // ---- radix refinement loop over 32-bit value bits (runs once normally) ----
    unsigned fmask = 0, prefix = 0;
    int shift = 21;
    int kbelow = 0;
    bool fellback = false;

    for (;;) {
        ((uint4*)hist)[tid]       = make_uint4(0u, 0u, 0u, 0u);
        ((uint4*)hist)[tid + 256] = make_uint4(0u, 0u, 0u, 0u);
        if (tid == 0) s_cnt = 0;
        __syncthreads();

        #pragma unroll
        for (int q = 0; q < 8; q++) {
            unsigned bq = bj[q];
            if ((bq & fmask) == prefix) {
                unsigned d = (bq >> shift) & 2047u;
                atomicAdd(&hist[((d & 7u) << 8) | (d >> 3)], 1u);
            }
        }
        __syncthreads();

        // superbin sums: thread tid covers original bins [tid*8, tid*8+8)
        unsigned v = 0;
        #pragma unroll
        for (int q = 0; q < 8; q++) v += hist[(q << 8) | tid];
        unsigned sc = v;
        #pragma unroll
        for (int o = 1; o < 32; o <<= 1) {
            unsigned n = __shfl_up_sync(0xffffffffu, sc, o);
            if (lane >= o) sc += n;
        }
        if (lane == 31) wtot[wid] = sc;
        __syncthreads();
        if (wid == 0) {
            unsigned w = (lane < 8) ? wtot[lane] : 0;
            #pragma unroll
            for (int o = 1; o < 8; o <<= 1) {
                unsigned n = __shfl_up_sync(0xffffffffu, w, o);
                if (lane >= o) w += n;
            }
            if (lane < 8) wtot[lane] = w;
        }
        __syncthreads();

        int kneed = KK - kbelow;
        unsigned incl = sc + (wid ? wtot[wid - 1] : 0);
        unsigned excl = incl - v;
        if ((int)incl >= kneed && (int)excl < kneed) { s_sb = tid; s_excl = (int)excl; }
        __syncthreads();
        if (tid == 0) {
            int sb = s_sb;
            unsigned cum = (unsigned)s_excl;
            int pd = sb * 8 + 7; unsigned hp = hist[(7u << 8) | sb];
            #pragma unroll
            for (int q = 0; q < 8; q++) {
                unsigned h = hist[(q << 8) | sb];
                if (cum + h >= (unsigned)kneed) { pd = sb * 8 + q; hp = h; break; }
                cum += h;
            }
            s_piv = pd; s_excl = (int)cum; s_histpiv = (int)hp;
        }
        __syncthreads();

        int below_total = kbelow + s_excl;           // strictly below pivot prefix
        unsigned nfmask  = fmask | (2047u << shift);
        unsigned nprefix = prefix | ((unsigned)s_piv << shift);

        if (below_total + s_histpiv <= CAP) {
            // compact: (bits masked to refined prefix) <= pivot prefix
            #pragma unroll
            for (int q = 0; q < 8; q++) {
                unsigned bq = bj[q];
                if ((bq & nfmask) <= nprefix) {
                    int pos = atomicAdd(&s_cnt, 1);
                    if (pos < CAP)
                        cand[pos] = ((unsigned long long)bq << 32)
                                  | (unsigned)(tid + q * 256);
                }
            }
            __syncthreads();
            break;
        }
        if (shift == 0) { fellback = true; break; }   // >CAP identical floats
        fmask = nfmask; prefix = nprefix;
        shift = (shift == 21) ? 10 : 0;
        kbelow = below_total;
        __syncthreads();
    }

    if (!fellback) {
        // ---- exact rank by O(C^2) broadcast comparisons ----
        int C = s_cnt; if (C > CAP) C = CAP;
        for (int t = tid; t < C; t += 256) {
            unsigned long long k = cand[t];
            int rank = 0;
            for (int c = 0; c < C; c++) rank += (cand[c] < k);
            if (rank < KK) emit(row, base, xi, cmi, rank, k, out);
        }
    } else {
        // ---- fallback: exact iterative min-extraction from registers ----
        unsigned taken = 0;
        for (int s = 0; s < KK; s++) {
            unsigned long long local = ~0ULL;
            #pragma unroll
            for (int q = 0; q < 8; q++) {
                unsigned long long k = ((unsigned long long)bj[q] << 32)
                                     | (unsigned)(tid + q * 256);
                if (!(taken & (1u << q))) local = umin64(local, k);
            }
            #pragma unroll
            for (int o = 16; o > 0; o >>= 1)
                local = umin64(local, __shfl_down_sync(0xffffffffu, local, o));
            if (lane == 0) ((unsigned long long*)hist)[wid] = local;
            __syncthreads();
            if (tid == 0) {
                unsigned long long m = ((unsigned long long*)hist)[0];
                #pragma unroll
                for (int w = 1; w < 8; w++)
                    m = umin64(m, ((unsigned long long*)hist)[w]);
                s_win = m;
                emit(row, base, xi, cmi, s, m, out);
            }
            __syncthreads();
            unsigned long long m = s_win;
            int j = (int)(unsigned)(m & 0xffffffffu);
            if ((j & 255) == tid) taken |= 1u << (j >> 8);
            __syncthreads();
        }
    }
}

extern "C" void kernel_launch(void* const* d_in, const int* in_sizes, int n_in,
                              void* d_out, int out_size) {
    const float* coords = (const float*)d_in[0];
    const void*  cm     = d_in[1];
    const int*   ridx   = (const int*)d_in[2];
    const void*  pm     = d_in[3];
    float* out = (float*)d_out;

    detect_kernel<<<1, 128>>>((const unsigned char*)cm);
    pack_kernel<<<(BN + 255) / 256, 256>>>(coords, cm, ridx, pm);
    features_kernel<<<(BN + 255) / 256, 256>>>(coords, out);
    topk_kernel<<<BN, 256>>>(out);
}